// round 13
// baseline (speedup 1.0000x reference)
#include <cuda_runtime.h>
#include <cstdint>

#define N_NODES 500000
#define N_EDGES 16000000

// ---------------- scratch (device globals; no allocation allowed) ----------
__device__ int    g_deg [N_NODES];
__device__ float  g_dinv[N_NODES];
__device__ float4 g_g1  [N_NODES];   // dinv-scaled layer-1 features
__device__ float4 g_S1  [N_NODES];   // layer-1 scatter accumulator
__device__ float2 g_g2  [N_NODES];   // dinv-scaled layer-2 features
__device__ float2 g_S2  [N_NODES];   // layer-2 scatter accumulator

// ---------------- vectorized L2 reductions (PTX ISA 8.1, sm_90+) -----------
__device__ __forceinline__ void red_add_v4(float4* addr, float4 v) {
    asm volatile("red.global.add.v4.f32 [%0], {%1, %2, %3, %4};"
                 :: "l"(addr), "f"(v.x), "f"(v.y), "f"(v.z), "f"(v.w)
                 : "memory");
}
__device__ __forceinline__ void red_add_v2(float2* addr, float2 v) {
    asm volatile("red.global.add.v2.f32 [%0], {%1, %2};"
                 :: "l"(addr), "f"(v.x), "f"(v.y)
                 : "memory");
}
// streaming (evict-first) index loads — keep L1 clean
__device__ __forceinline__ int4 ldcs_int4(const int* p) {
    return __ldcs(reinterpret_cast<const int4*>(p));
}
__device__ __forceinline__ int2 ldcs_int2(const int* p) {
    return __ldcs(reinterpret_cast<const int2*>(p));
}

// ---------------- edge kernels --------------------------------------------
// degree from target (col) indices; 4 edges per thread (proven shape)
__global__ void __launch_bounds__(256) k_degree(const int* __restrict__ col) {
    int t = blockIdx.x * blockDim.x + threadIdx.x;
    int base = t * 4;
    if (base >= N_EDGES) return;
    int4 c = ldcs_int4(col + base);
    atomicAdd(&g_deg[c.x], 1);
    atomicAdd(&g_deg[c.y], 1);
    atomicAdd(&g_deg[c.z], 1);
    atomicAdd(&g_deg[c.w], 1);
}

// layer-1 edge scatter: S1[col] += g1[row]  — EPT=2, TB=512 (fewer block
// dispatch/retire events at identical warp count and per-thread work)
__global__ void __launch_bounds__(512) k_scatter1(const int* __restrict__ row,
                                                  const int* __restrict__ col) {
    int t = blockIdx.x * blockDim.x + threadIdx.x;
    int base = t * 2;
    if (base >= N_EDGES) return;
    int2 r = ldcs_int2(row + base);
    int2 c = ldcs_int2(col + base);
    float4 v0 = __ldcg(&g_g1[r.x]);
    float4 v1 = __ldcg(&g_g1[r.y]);
    red_add_v4(&g_S1[c.x], v0);
    red_add_v4(&g_S1[c.y], v1);
}

// layer-2 edge scatter: S2[col] += g2[row]  — EPT=2, TB=512
__global__ void __launch_bounds__(512) k_scatter2(const int* __restrict__ row,
                                                  const int* __restrict__ col) {
    int t = blockIdx.x * blockDim.x + threadIdx.x;
    int base = t * 2;
    if (base >= N_EDGES) return;
    int2 r = ldcs_int2(row + base);
    int2 c = ldcs_int2(col + base);
    float2 v0 = __ldcg(&g_g2[r.x]);
    float2 v1 = __ldcg(&g_g2[r.y]);
    red_add_v2(&g_S2[c.x], v0);
    red_add_v2(&g_S2[c.y], v1);
}

// ---------------- node kernels (proven shape: 1 node/thread) ----------------
// h1 = x @ W1 (unscaled) -> g_g1; also zero S1,S2. Side stream, hidden
// under k_degree.
__global__ void k_matmul1(const float* __restrict__ x,
                          const float* __restrict__ W1) {
    int i = blockIdx.x * blockDim.x + threadIdx.x;
    if (i >= N_NODES) return;
    const float* xr = x + (long long)i * 9;
    float h0 = 0.f, h1 = 0.f, h2 = 0.f, h3 = 0.f;
#pragma unroll
    for (int k = 0; k < 9; ++k) {
        float xv = __ldg(xr + k);
        h0 += xv * __ldg(W1 + k * 4 + 0);
        h1 += xv * __ldg(W1 + k * 4 + 1);
        h2 += xv * __ldg(W1 + k * 4 + 2);
        h3 += xv * __ldg(W1 + k * 4 + 3);
    }
    g_g1[i] = make_float4(h0, h1, h2, h3);
    g_S1[i] = make_float4(0.f, 0.f, 0.f, 0.f);
    g_S2[i] = make_float2(0.f, 0.f);
}

// after degree+matmul: dinv, g1 *= dinv
__global__ void k_scale1() {
    int i = blockIdx.x * blockDim.x + threadIdx.x;
    if (i >= N_NODES) return;
    float d = rsqrtf((float)g_deg[i] + 1.0f);
    g_dinv[i] = d;
    float4 h = g_g1[i];
    g_g1[i] = make_float4(h.x * d, h.y * d, h.z * d, h.w * d);
}

// per-node: t = tanh(dinv*(S1+g1)+b1); g2 = (t @ W2) * dinv
__global__ void k_layer2(const float* __restrict__ W2,
                         const float* __restrict__ b1) {
    int i = blockIdx.x * blockDim.x + threadIdx.x;
    if (i >= N_NODES) return;
    float d  = g_dinv[i];
    float4 s = g_S1[i];
    float4 g = g_g1[i];
    float t0 = tanhf(d * (s.x + g.x) + __ldg(b1 + 0));
    float t1 = tanhf(d * (s.y + g.y) + __ldg(b1 + 1));
    float t2 = tanhf(d * (s.z + g.z) + __ldg(b1 + 2));
    float t3 = tanhf(d * (s.w + g.w) + __ldg(b1 + 3));
    float u0 = t0 * __ldg(W2 + 0) + t1 * __ldg(W2 + 2) + t2 * __ldg(W2 + 4) + t3 * __ldg(W2 + 6);
    float u1 = t0 * __ldg(W2 + 1) + t1 * __ldg(W2 + 3) + t2 * __ldg(W2 + 5) + t3 * __ldg(W2 + 7);
    g_g2[i] = make_float2(u0 * d, u1 * d);
}

// finalize: out = dinv*(S2+g2) + b2
__global__ void k_final(float2* __restrict__ out,
                        const float* __restrict__ b2) {
    int i = blockIdx.x * blockDim.x + threadIdx.x;
    if (i >= N_NODES) return;
    float d  = g_dinv[i];
    float2 s = g_S2[i];
    float2 g = g_g2[i];
    out[i] = make_float2(d * (s.x + g.x) + __ldg(b2 + 0),
                         d * (s.y + g.y) + __ldg(b2 + 1));
}

// ---------------- launch -----------------------------------------------------
extern "C" void kernel_launch(void* const* d_in, const int* in_sizes, int n_in,
                              void* d_out, int out_size) {
    const float* x  = (const float*)d_in[0];
    const int*   ei = (const int*)d_in[1];     // [2, 16M] int32
    const float* W1 = (const float*)d_in[2];   // [9,4]
    const float* b1 = (const float*)d_in[3];   // [4]
    const float* W2 = (const float*)d_in[4];   // [4,2]
    const float* b2 = (const float*)d_in[5];   // [2]
    float2*      out = (float2*)d_out;         // [N,2] f32

    const int* row = ei;
    const int* col = ei + N_EDGES;

    const int TB  = 256;
    const int TBS = 512;   // scatter block size
    const int node_blocks  = (N_NODES + TB - 1) / TB;
    const int edge_blocks4 = (N_EDGES / 4 + TB - 1) / TB;
    const int scat_blocks  = (N_EDGES / 2 + TBS - 1) / TBS;

    static cudaStream_t s2 = nullptr;
    static cudaEvent_t ev_fork = nullptr, ev_join = nullptr;
    static void* deg_ptr = nullptr;
    if (!s2) {
        cudaStreamCreateWithFlags(&s2, cudaStreamNonBlocking);
        cudaEventCreateWithFlags(&ev_fork, cudaEventDisableTiming);
        cudaEventCreateWithFlags(&ev_join, cudaEventDisableTiming);
        cudaGetSymbolAddress(&deg_ptr, g_deg);
    }

    cudaStream_t s0 = (cudaStream_t)0;   // capture/main stream

    // zero degree counters (async memset is graph-capturable)
    cudaMemsetAsync(deg_ptr, 0, N_NODES * sizeof(int), s0);

    // fork: matmul1 (+ S1/S2 zeroing) on s2, concurrent with degree on s0
    cudaEventRecord(ev_fork, s0);
    cudaStreamWaitEvent(s2, ev_fork, 0);
    k_matmul1<<<node_blocks, TB, 0, s2>>>(x, W1);
    cudaEventRecord(ev_join, s2);

    k_degree<<<edge_blocks4, TB, 0, s0>>>(col);

    // join
    cudaStreamWaitEvent(s0, ev_join, 0);

    k_scale1  <<<node_blocks, TB,  0, s0>>>();
    k_scatter1<<<scat_blocks, TBS, 0, s0>>>(row, col);
    k_layer2  <<<node_blocks, TB,  0, s0>>>(W2, b1);
    k_scatter2<<<scat_blocks, TBS, 0, s0>>>(row, col);
    k_final   <<<node_blocks, TB,  0, s0>>>(out, b2);
}

// round 14
// speedup vs baseline: 1.0018x; 1.0018x over previous
#include <cuda_runtime.h>
#include <cstdint>

#define N_NODES 500000
#define N_EDGES 16000000

// ---------------- scratch (device globals; no allocation allowed) ----------
__device__ int    g_deg [N_NODES];
__device__ float  g_dinv[N_NODES];
__device__ float4 g_g1  [N_NODES];   // dinv-scaled layer-1 features
__device__ float4 g_S1  [N_NODES];   // layer-1 scatter accumulator
__device__ float2 g_g2  [N_NODES];   // dinv-scaled layer-2 features
__device__ float2 g_S2  [N_NODES];   // layer-2 scatter accumulator

// ---------------- vectorized L2 reductions (PTX ISA 8.1, sm_90+) -----------
__device__ __forceinline__ void red_add_v4(float4* addr, float4 v) {
    asm volatile("red.global.add.v4.f32 [%0], {%1, %2, %3, %4};"
                 :: "l"(addr), "f"(v.x), "f"(v.y), "f"(v.z), "f"(v.w)
                 : "memory");
}
__device__ __forceinline__ void red_add_v2(float2* addr, float2 v) {
    asm volatile("red.global.add.v2.f32 [%0], {%1, %2};"
                 :: "l"(addr), "f"(v.x), "f"(v.y)
                 : "memory");
}
// streaming (evict-first) index loads — keep L1 clean
__device__ __forceinline__ int4 ldcs_int4(const int* p) {
    return __ldcs(reinterpret_cast<const int4*>(p));
}
__device__ __forceinline__ int2 ldcs_int2(const int* p) {
    return __ldcs(reinterpret_cast<const int2*>(p));
}

// ---------------- edge kernels --------------------------------------------
// degree from target (col) indices; 4 edges per thread (proven shape)
__global__ void __launch_bounds__(256) k_degree(const int* __restrict__ col) {
    int t = blockIdx.x * blockDim.x + threadIdx.x;
    int base = t * 4;
    if (base >= N_EDGES) return;
    int4 c = ldcs_int4(col + base);
    atomicAdd(&g_deg[c.x], 1);
    atomicAdd(&g_deg[c.y], 1);
    atomicAdd(&g_deg[c.z], 1);
    atomicAdd(&g_deg[c.w], 1);
}

// layer-1 edge scatter: S1[col] += g1[row]  — EPT=2, TB=256 (measured optimum)
__global__ void __launch_bounds__(256) k_scatter1(const int* __restrict__ row,
                                                  const int* __restrict__ col) {
    int t = blockIdx.x * blockDim.x + threadIdx.x;
    int base = t * 2;
    if (base >= N_EDGES) return;
    int2 r = ldcs_int2(row + base);
    int2 c = ldcs_int2(col + base);
    float4 v0 = __ldcg(&g_g1[r.x]);
    float4 v1 = __ldcg(&g_g1[r.y]);
    red_add_v4(&g_S1[c.x], v0);
    red_add_v4(&g_S1[c.y], v1);
}

// layer-2 edge scatter: S2[col] += g2[row]  — EPT=2, TB=256
__global__ void __launch_bounds__(256) k_scatter2(const int* __restrict__ row,
                                                  const int* __restrict__ col) {
    int t = blockIdx.x * blockDim.x + threadIdx.x;
    int base = t * 2;
    if (base >= N_EDGES) return;
    int2 r = ldcs_int2(row + base);
    int2 c = ldcs_int2(col + base);
    float2 v0 = __ldcg(&g_g2[r.x]);
    float2 v1 = __ldcg(&g_g2[r.y]);
    red_add_v2(&g_S2[c.x], v0);
    red_add_v2(&g_S2[c.y], v1);
}

// ---------------- node kernels (proven shape: 1 node/thread) ----------------
// h1 = x @ W1 (unscaled) -> g_g1; also zero S1,S2. Side stream, hidden
// under k_degree.
__global__ void k_matmul1(const float* __restrict__ x,
                          const float* __restrict__ W1) {
    int i = blockIdx.x * blockDim.x + threadIdx.x;
    if (i >= N_NODES) return;
    const float* xr = x + (long long)i * 9;
    float h0 = 0.f, h1 = 0.f, h2 = 0.f, h3 = 0.f;
#pragma unroll
    for (int k = 0; k < 9; ++k) {
        float xv = __ldg(xr + k);
        h0 += xv * __ldg(W1 + k * 4 + 0);
        h1 += xv * __ldg(W1 + k * 4 + 1);
        h2 += xv * __ldg(W1 + k * 4 + 2);
        h3 += xv * __ldg(W1 + k * 4 + 3);
    }
    g_g1[i] = make_float4(h0, h1, h2, h3);
    g_S1[i] = make_float4(0.f, 0.f, 0.f, 0.f);
    g_S2[i] = make_float2(0.f, 0.f);
}

// after degree+matmul: dinv, g1 *= dinv
__global__ void k_scale1() {
    int i = blockIdx.x * blockDim.x + threadIdx.x;
    if (i >= N_NODES) return;
    float d = rsqrtf((float)g_deg[i] + 1.0f);
    g_dinv[i] = d;
    float4 h = g_g1[i];
    g_g1[i] = make_float4(h.x * d, h.y * d, h.z * d, h.w * d);
}

// per-node: t = tanh(dinv*(S1+g1)+b1); g2 = (t @ W2) * dinv
__global__ void k_layer2(const float* __restrict__ W2,
                         const float* __restrict__ b1) {
    int i = blockIdx.x * blockDim.x + threadIdx.x;
    if (i >= N_NODES) return;
    float d  = g_dinv[i];
    float4 s = g_S1[i];
    float4 g = g_g1[i];
    float t0 = tanhf(d * (s.x + g.x) + __ldg(b1 + 0));
    float t1 = tanhf(d * (s.y + g.y) + __ldg(b1 + 1));
    float t2 = tanhf(d * (s.z + g.z) + __ldg(b1 + 2));
    float t3 = tanhf(d * (s.w + g.w) + __ldg(b1 + 3));
    float u0 = t0 * __ldg(W2 + 0) + t1 * __ldg(W2 + 2) + t2 * __ldg(W2 + 4) + t3 * __ldg(W2 + 6);
    float u1 = t0 * __ldg(W2 + 1) + t1 * __ldg(W2 + 3) + t2 * __ldg(W2 + 5) + t3 * __ldg(W2 + 7);
    g_g2[i] = make_float2(u0 * d, u1 * d);
}

// finalize: out = dinv*(S2+g2) + b2
__global__ void k_final(float2* __restrict__ out,
                        const float* __restrict__ b2) {
    int i = blockIdx.x * blockDim.x + threadIdx.x;
    if (i >= N_NODES) return;
    float d  = g_dinv[i];
    float2 s = g_S2[i];
    float2 g = g_g2[i];
    out[i] = make_float2(d * (s.x + g.x) + __ldg(b2 + 0),
                         d * (s.y + g.y) + __ldg(b2 + 1));
}

// ---------------- launch -----------------------------------------------------
extern "C" void kernel_launch(void* const* d_in, const int* in_sizes, int n_in,
                              void* d_out, int out_size) {
    const float* x  = (const float*)d_in[0];
    const int*   ei = (const int*)d_in[1];     // [2, 16M] int32
    const float* W1 = (const float*)d_in[2];   // [9,4]
    const float* b1 = (const float*)d_in[3];   // [4]
    const float* W2 = (const float*)d_in[4];   // [4,2]
    const float* b2 = (const float*)d_in[5];   // [2]
    float2*      out = (float2*)d_out;         // [N,2] f32

    const int* row = ei;
    const int* col = ei + N_EDGES;

    const int TB = 256;
    const int node_blocks  = (N_NODES + TB - 1) / TB;
    const int edge_blocks4 = (N_EDGES / 4 + TB - 1) / TB;
    const int edge_blocks2 = (N_EDGES / 2 + TB - 1) / TB;

    static cudaStream_t s2 = nullptr;
    static cudaEvent_t ev_fork = nullptr, ev_join = nullptr;
    static void* deg_ptr = nullptr;
    if (!s2) {
        cudaStreamCreateWithFlags(&s2, cudaStreamNonBlocking);
        cudaEventCreateWithFlags(&ev_fork, cudaEventDisableTiming);
        cudaEventCreateWithFlags(&ev_join, cudaEventDisableTiming);
        cudaGetSymbolAddress(&deg_ptr, g_deg);
    }

    cudaStream_t s0 = (cudaStream_t)0;   // capture/main stream

    // zero degree counters (async memset is graph-capturable)
    cudaMemsetAsync(deg_ptr, 0, N_NODES * sizeof(int), s0);

    // fork: matmul1 (+ S1/S2 zeroing) on s2, concurrent with degree on s0
    cudaEventRecord(ev_fork, s0);
    cudaStreamWaitEvent(s2, ev_fork, 0);
    k_matmul1<<<node_blocks, TB, 0, s2>>>(x, W1);
    cudaEventRecord(ev_join, s2);

    k_degree<<<edge_blocks4, TB, 0, s0>>>(col);

    // join
    cudaStreamWaitEvent(s0, ev_join, 0);

    k_scale1  <<<node_blocks,  TB, 0, s0>>>();
    k_scatter1<<<edge_blocks2, TB, 0, s0>>>(row, col);
    k_layer2  <<<node_blocks,  TB, 0, s0>>>(W2, b1);
    k_scatter2<<<edge_blocks2, TB, 0, s0>>>(row, col);
    k_final   <<<node_blocks,  TB, 0, s0>>>(out, b2);
}

// round 15
// speedup vs baseline: 1.0060x; 1.0042x over previous
#include <cuda_runtime.h>
#include <cstdint>

#define N_NODES 500000
#define N_EDGES 16000000

// ---------------- scratch (device globals; no allocation allowed) ----------
__device__ int    g_deg [N_NODES];
__device__ float  g_dinv[N_NODES];
__device__ float4 g_g1  [N_NODES];   // dinv-scaled layer-1 features
__device__ float4 g_S1  [N_NODES];   // layer-1 scatter accumulator
__device__ float2 g_g2  [N_NODES];   // dinv-scaled layer-2 features
__device__ float2 g_S2  [N_NODES];   // layer-2 scatter accumulator

// ---------------- vectorized L2 reductions (PTX ISA 8.1, sm_90+) -----------
__device__ __forceinline__ void red_add_v4(float4* addr, float4 v) {
    asm volatile("red.global.add.v4.f32 [%0], {%1, %2, %3, %4};"
                 :: "l"(addr), "f"(v.x), "f"(v.y), "f"(v.z), "f"(v.w)
                 : "memory");
}
__device__ __forceinline__ void red_add_v2(float2* addr, float2 v) {
    asm volatile("red.global.add.v2.f32 [%0], {%1, %2};"
                 :: "l"(addr), "f"(v.x), "f"(v.y)
                 : "memory");
}
// streaming (evict-first) index loads — keep L1 clean
__device__ __forceinline__ int4 ldcs_int4(const int* p) {
    return __ldcs(reinterpret_cast<const int4*>(p));
}
__device__ __forceinline__ int2 ldcs_int2(const int* p) {
    return __ldcs(reinterpret_cast<const int2*>(p));
}

// ---------------- edge kernels --------------------------------------------
// degree from target (col) indices; 4 edges per thread (proven shape)
__global__ void __launch_bounds__(256) k_degree(const int* __restrict__ col) {
    int t = blockIdx.x * blockDim.x + threadIdx.x;
    int base = t * 4;
    if (base >= N_EDGES) return;
    int4 c = ldcs_int4(col + base);
    atomicAdd(&g_deg[c.x], 1);
    atomicAdd(&g_deg[c.y], 1);
    atomicAdd(&g_deg[c.z], 1);
    atomicAdd(&g_deg[c.w], 1);
}

// layer-1 edge scatter: S1[col] += g1[row]  — EPT=2, TB=256 (measured optimum)
__global__ void __launch_bounds__(256) k_scatter1(const int* __restrict__ row,
                                                  const int* __restrict__ col) {
    int t = blockIdx.x * blockDim.x + threadIdx.x;
    int base = t * 2;
    if (base >= N_EDGES) return;
    int2 r = ldcs_int2(row + base);
    int2 c = ldcs_int2(col + base);
    float4 v0 = __ldcg(&g_g1[r.x]);
    float4 v1 = __ldcg(&g_g1[r.y]);
    red_add_v4(&g_S1[c.x], v0);
    red_add_v4(&g_S1[c.y], v1);
}

// layer-2 edge scatter: S2[col] += g2[row]  — EPT=2, TB=256
__global__ void __launch_bounds__(256) k_scatter2(const int* __restrict__ row,
                                                  const int* __restrict__ col) {
    int t = blockIdx.x * blockDim.x + threadIdx.x;
    int base = t * 2;
    if (base >= N_EDGES) return;
    int2 r = ldcs_int2(row + base);
    int2 c = ldcs_int2(col + base);
    float2 v0 = __ldcg(&g_g2[r.x]);
    float2 v1 = __ldcg(&g_g2[r.y]);
    red_add_v2(&g_S2[c.x], v0);
    red_add_v2(&g_S2[c.y], v1);
}

// ---------------- node kernels (proven shape: 1 node/thread) ----------------
// h1 = x @ W1 (unscaled) -> g_g1; also zero S1,S2. Side stream, hidden
// under k_degree.
__global__ void k_matmul1(const float* __restrict__ x,
                          const float* __restrict__ W1) {
    int i = blockIdx.x * blockDim.x + threadIdx.x;
    if (i >= N_NODES) return;
    const float* xr = x + (long long)i * 9;
    float h0 = 0.f, h1 = 0.f, h2 = 0.f, h3 = 0.f;
#pragma unroll
    for (int k = 0; k < 9; ++k) {
        float xv = __ldg(xr + k);
        h0 += xv * __ldg(W1 + k * 4 + 0);
        h1 += xv * __ldg(W1 + k * 4 + 1);
        h2 += xv * __ldg(W1 + k * 4 + 2);
        h3 += xv * __ldg(W1 + k * 4 + 3);
    }
    g_g1[i] = make_float4(h0, h1, h2, h3);
    g_S1[i] = make_float4(0.f, 0.f, 0.f, 0.f);
    g_S2[i] = make_float2(0.f, 0.f);
}

// after degree+matmul: dinv, g1 *= dinv
__global__ void k_scale1() {
    int i = blockIdx.x * blockDim.x + threadIdx.x;
    if (i >= N_NODES) return;
    float d = rsqrtf((float)g_deg[i] + 1.0f);
    g_dinv[i] = d;
    float4 h = g_g1[i];
    g_g1[i] = make_float4(h.x * d, h.y * d, h.z * d, h.w * d);
}

// per-node: t = tanh(dinv*(S1+g1)+b1); g2 = (t @ W2) * dinv
__global__ void k_layer2(const float* __restrict__ W2,
                         const float* __restrict__ b1) {
    int i = blockIdx.x * blockDim.x + threadIdx.x;
    if (i >= N_NODES) return;
    float d  = g_dinv[i];
    float4 s = g_S1[i];
    float4 g = g_g1[i];
    float t0 = tanhf(d * (s.x + g.x) + __ldg(b1 + 0));
    float t1 = tanhf(d * (s.y + g.y) + __ldg(b1 + 1));
    float t2 = tanhf(d * (s.z + g.z) + __ldg(b1 + 2));
    float t3 = tanhf(d * (s.w + g.w) + __ldg(b1 + 3));
    float u0 = t0 * __ldg(W2 + 0) + t1 * __ldg(W2 + 2) + t2 * __ldg(W2 + 4) + t3 * __ldg(W2 + 6);
    float u1 = t0 * __ldg(W2 + 1) + t1 * __ldg(W2 + 3) + t2 * __ldg(W2 + 5) + t3 * __ldg(W2 + 7);
    g_g2[i] = make_float2(u0 * d, u1 * d);
}

// finalize: out = dinv*(S2+g2) + b2
__global__ void k_final(float2* __restrict__ out,
                        const float* __restrict__ b2) {
    int i = blockIdx.x * blockDim.x + threadIdx.x;
    if (i >= N_NODES) return;
    float d  = g_dinv[i];
    float2 s = g_S2[i];
    float2 g = g_g2[i];
    out[i] = make_float2(d * (s.x + g.x) + __ldg(b2 + 0),
                         d * (s.y + g.y) + __ldg(b2 + 1));
}

// ---------------- launch -----------------------------------------------------
extern "C" void kernel_launch(void* const* d_in, const int* in_sizes, int n_in,
                              void* d_out, int out_size) {
    const float* x  = (const float*)d_in[0];
    const int*   ei = (const int*)d_in[1];     // [2, 16M] int32
    const float* W1 = (const float*)d_in[2];   // [9,4]
    const float* b1 = (const float*)d_in[3];   // [4]
    const float* W2 = (const float*)d_in[4];   // [4,2]
    const float* b2 = (const float*)d_in[5];   // [2]
    float2*      out = (float2*)d_out;         // [N,2] f32

    const int* row = ei;
    const int* col = ei + N_EDGES;

    const int TB = 256;
    const int node_blocks  = (N_NODES + TB - 1) / TB;
    const int edge_blocks4 = (N_EDGES / 4 + TB - 1) / TB;
    const int edge_blocks2 = (N_EDGES / 2 + TB - 1) / TB;

    static cudaStream_t s2 = nullptr;
    static cudaEvent_t ev_fork = nullptr, ev_join = nullptr;
    static void* deg_ptr = nullptr;
    if (!s2) {
        cudaStreamCreateWithFlags(&s2, cudaStreamNonBlocking);
        cudaEventCreateWithFlags(&ev_fork, cudaEventDisableTiming);
        cudaEventCreateWithFlags(&ev_join, cudaEventDisableTiming);
        cudaGetSymbolAddress(&deg_ptr, g_deg);
    }

    cudaStream_t s0 = (cudaStream_t)0;   // capture/main stream

    // zero degree counters (async memset is graph-capturable)
    cudaMemsetAsync(deg_ptr, 0, N_NODES * sizeof(int), s0);

    // fork: matmul1 (+ S1/S2 zeroing) on s2, concurrent with degree on s0
    cudaEventRecord(ev_fork, s0);
    cudaStreamWaitEvent(s2, ev_fork, 0);
    k_matmul1<<<node_blocks, TB, 0, s2>>>(x, W1);
    cudaEventRecord(ev_join, s2);

    k_degree<<<edge_blocks4, TB, 0, s0>>>(col);

    // join
    cudaStreamWaitEvent(s0, ev_join, 0);

    k_scale1  <<<node_blocks,  TB, 0, s0>>>();
    k_scatter1<<<edge_blocks2, TB, 0, s0>>>(row, col);
    k_layer2  <<<node_blocks,  TB, 0, s0>>>(W2, b1);
    k_scatter2<<<edge_blocks2, TB, 0, s0>>>(row, col);
    k_final   <<<node_blocks,  TB, 0, s0>>>(out, b2);
}

// round 16
// speedup vs baseline: 1.0070x; 1.0010x over previous
#include <cuda_runtime.h>
#include <cstdint>

#define N_NODES 500000
#define N_EDGES 16000000

// ---------------- scratch (device globals; no allocation allowed) ----------
__device__ int    g_deg [N_NODES];
__device__ float  g_dinv[N_NODES];
__device__ float4 g_g1  [N_NODES];   // dinv-scaled layer-1 features
__device__ float4 g_S1  [N_NODES];   // layer-1 scatter accumulator
__device__ float2 g_g2  [N_NODES];   // dinv-scaled layer-2 features
__device__ float2 g_S2  [N_NODES];   // layer-2 scatter accumulator

// ---------------- vectorized L2 reductions (PTX ISA 8.1, sm_90+) -----------
__device__ __forceinline__ void red_add_v4(float4* addr, float4 v) {
    asm volatile("red.global.add.v4.f32 [%0], {%1, %2, %3, %4};"
                 :: "l"(addr), "f"(v.x), "f"(v.y), "f"(v.z), "f"(v.w)
                 : "memory");
}
__device__ __forceinline__ void red_add_v2(float2* addr, float2 v) {
    asm volatile("red.global.add.v2.f32 [%0], {%1, %2};"
                 :: "l"(addr), "f"(v.x), "f"(v.y)
                 : "memory");
}
// streaming (evict-first) index loads — keep L1 clean
__device__ __forceinline__ int4 ldcs_int4(const int* p) {
    return __ldcs(reinterpret_cast<const int4*>(p));
}
__device__ __forceinline__ int2 ldcs_int2(const int* p) {
    return __ldcs(reinterpret_cast<const int2*>(p));
}

// ---------------- edge kernels --------------------------------------------
// degree from target (col) indices; 4 edges per thread (proven shape)
__global__ void __launch_bounds__(256) k_degree(const int* __restrict__ col) {
    int t = blockIdx.x * blockDim.x + threadIdx.x;
    int base = t * 4;
    if (base >= N_EDGES) return;
    int4 c = ldcs_int4(col + base);
    atomicAdd(&g_deg[c.x], 1);
    atomicAdd(&g_deg[c.y], 1);
    atomicAdd(&g_deg[c.z], 1);
    atomicAdd(&g_deg[c.w], 1);
}

// layer-1 edge scatter: S1[col] += g1[row]  — EPT=2, TB=256 (measured optimum)
__global__ void __launch_bounds__(256) k_scatter1(const int* __restrict__ row,
                                                  const int* __restrict__ col) {
    int t = blockIdx.x * blockDim.x + threadIdx.x;
    int base = t * 2;
    if (base >= N_EDGES) return;
    int2 r = ldcs_int2(row + base);
    int2 c = ldcs_int2(col + base);
    float4 v0 = __ldcg(&g_g1[r.x]);
    float4 v1 = __ldcg(&g_g1[r.y]);
    red_add_v4(&g_S1[c.x], v0);
    red_add_v4(&g_S1[c.y], v1);
}

// layer-2 edge scatter: S2[col] += g2[row]  — EPT=2, TB=256
__global__ void __launch_bounds__(256) k_scatter2(const int* __restrict__ row,
                                                  const int* __restrict__ col) {
    int t = blockIdx.x * blockDim.x + threadIdx.x;
    int base = t * 2;
    if (base >= N_EDGES) return;
    int2 r = ldcs_int2(row + base);
    int2 c = ldcs_int2(col + base);
    float2 v0 = __ldcg(&g_g2[r.x]);
    float2 v1 = __ldcg(&g_g2[r.y]);
    red_add_v2(&g_S2[c.x], v0);
    red_add_v2(&g_S2[c.y], v1);
}

// ---------------- node kernels (proven shape: 1 node/thread) ----------------
// h1 = x @ W1 (unscaled) -> g_g1; also zero S1,S2. Side stream, hidden
// under k_degree.
__global__ void k_matmul1(const float* __restrict__ x,
                          const float* __restrict__ W1) {
    int i = blockIdx.x * blockDim.x + threadIdx.x;
    if (i >= N_NODES) return;
    const float* xr = x + (long long)i * 9;
    float h0 = 0.f, h1 = 0.f, h2 = 0.f, h3 = 0.f;
#pragma unroll
    for (int k = 0; k < 9; ++k) {
        float xv = __ldg(xr + k);
        h0 += xv * __ldg(W1 + k * 4 + 0);
        h1 += xv * __ldg(W1 + k * 4 + 1);
        h2 += xv * __ldg(W1 + k * 4 + 2);
        h3 += xv * __ldg(W1 + k * 4 + 3);
    }
    g_g1[i] = make_float4(h0, h1, h2, h3);
    g_S1[i] = make_float4(0.f, 0.f, 0.f, 0.f);
    g_S2[i] = make_float2(0.f, 0.f);
}

// after degree+matmul: dinv, g1 *= dinv
__global__ void k_scale1() {
    int i = blockIdx.x * blockDim.x + threadIdx.x;
    if (i >= N_NODES) return;
    float d = rsqrtf((float)g_deg[i] + 1.0f);
    g_dinv[i] = d;
    float4 h = g_g1[i];
    g_g1[i] = make_float4(h.x * d, h.y * d, h.z * d, h.w * d);
}

// per-node: t = tanh(dinv*(S1+g1)+b1); g2 = (t @ W2) * dinv
__global__ void k_layer2(const float* __restrict__ W2,
                         const float* __restrict__ b1) {
    int i = blockIdx.x * blockDim.x + threadIdx.x;
    if (i >= N_NODES) return;
    float d  = g_dinv[i];
    float4 s = g_S1[i];
    float4 g = g_g1[i];
    float t0 = tanhf(d * (s.x + g.x) + __ldg(b1 + 0));
    float t1 = tanhf(d * (s.y + g.y) + __ldg(b1 + 1));
    float t2 = tanhf(d * (s.z + g.z) + __ldg(b1 + 2));
    float t3 = tanhf(d * (s.w + g.w) + __ldg(b1 + 3));
    float u0 = t0 * __ldg(W2 + 0) + t1 * __ldg(W2 + 2) + t2 * __ldg(W2 + 4) + t3 * __ldg(W2 + 6);
    float u1 = t0 * __ldg(W2 + 1) + t1 * __ldg(W2 + 3) + t2 * __ldg(W2 + 5) + t3 * __ldg(W2 + 7);
    g_g2[i] = make_float2(u0 * d, u1 * d);
}

// finalize: out = dinv*(S2+g2) + b2
__global__ void k_final(float2* __restrict__ out,
                        const float* __restrict__ b2) {
    int i = blockIdx.x * blockDim.x + threadIdx.x;
    if (i >= N_NODES) return;
    float d  = g_dinv[i];
    float2 s = g_S2[i];
    float2 g = g_g2[i];
    out[i] = make_float2(d * (s.x + g.x) + __ldg(b2 + 0),
                         d * (s.y + g.y) + __ldg(b2 + 1));
}

// ---------------- launch -----------------------------------------------------
extern "C" void kernel_launch(void* const* d_in, const int* in_sizes, int n_in,
                              void* d_out, int out_size) {
    const float* x  = (const float*)d_in[0];
    const int*   ei = (const int*)d_in[1];     // [2, 16M] int32
    const float* W1 = (const float*)d_in[2];   // [9,4]
    const float* b1 = (const float*)d_in[3];   // [4]
    const float* W2 = (const float*)d_in[4];   // [4,2]
    const float* b2 = (const float*)d_in[5];   // [2]
    float2*      out = (float2*)d_out;         // [N,2] f32

    const int* row = ei;
    const int* col = ei + N_EDGES;

    const int TB = 256;
    const int node_blocks  = (N_NODES + TB - 1) / TB;
    const int edge_blocks4 = (N_EDGES / 4 + TB - 1) / TB;
    const int edge_blocks2 = (N_EDGES / 2 + TB - 1) / TB;

    static cudaStream_t s2 = nullptr;
    static cudaEvent_t ev_fork = nullptr, ev_join = nullptr;
    static void* deg_ptr = nullptr;
    if (!s2) {
        cudaStreamCreateWithFlags(&s2, cudaStreamNonBlocking);
        cudaEventCreateWithFlags(&ev_fork, cudaEventDisableTiming);
        cudaEventCreateWithFlags(&ev_join, cudaEventDisableTiming);
        cudaGetSymbolAddress(&deg_ptr, g_deg);
    }

    cudaStream_t s0 = (cudaStream_t)0;   // capture/main stream

    // zero degree counters (async memset is graph-capturable)
    cudaMemsetAsync(deg_ptr, 0, N_NODES * sizeof(int), s0);

    // fork: matmul1 (+ S1/S2 zeroing) on s2, concurrent with degree on s0
    cudaEventRecord(ev_fork, s0);
    cudaStreamWaitEvent(s2, ev_fork, 0);
    k_matmul1<<<node_blocks, TB, 0, s2>>>(x, W1);
    cudaEventRecord(ev_join, s2);

    k_degree<<<edge_blocks4, TB, 0, s0>>>(col);

    // join
    cudaStreamWaitEvent(s0, ev_join, 0);

    k_scale1  <<<node_blocks,  TB, 0, s0>>>();
    k_scatter1<<<edge_blocks2, TB, 0, s0>>>(row, col);
    k_layer2  <<<node_blocks,  TB, 0, s0>>>(W2, b1);
    k_scatter2<<<edge_blocks2, TB, 0, s0>>>(row, col);
    k_final   <<<node_blocks,  TB, 0, s0>>>(out, b2);
}